// round 10
// baseline (speedup 1.0000x reference)
#include <cuda_runtime.h>
#include <cuda_bf16.h>
#include <cstdint>

// Problem constants
#define H 64
#define B 16
#define L 512
#define OUT 2
#define TOKS_PER_BLOCK 16
#define BLOCKS_PER_BATCH (2 * L / TOKS_PER_BLOCK)    // 64
#define GRID1 (B * BLOCKS_PER_BATCH)                 // 1024

// Pre-activation accumulator: y[b][j] = sum over tokens of (sos @ M_tok) @ w1^T.
// Zero at module load; the epilogue kernel resets it after reading, so every
// graph replay sees it zeroed.
__device__ float g_y[B * H];

// ---------------------------------------------------------------------------
// Kernel 1: token gather + sos contraction + DISTRIBUTED first MLP layer.
// The first linear layer is linear in h, so each block applies w1 to its
// partial h and atomically accumulates into pre-activation g_y. The extra
// 64x64 matvec (16 FMA/thread, w1 L1-cached) hides under DRAM latency.
// ---------------------------------------------------------------------------
__global__ __launch_bounds__(256, 4)
void gather_contract_kernel(const int* __restrict__ s1,
                            const int* __restrict__ s2,
                            const float4* __restrict__ embed,
                            const float* __restrict__ sos,
                            const float* __restrict__ w1)
{
    const int bl  = blockIdx.x;
    const int b   = bl / BLOCKS_PER_BATCH;
    const int j0  = (bl % BLOCKS_PER_BATCH) * TOKS_PER_BLOCK;  // within [0, 1024)
    const int tid = threadIdx.x;
    const int h4  = tid & 15;
    const int wg  = tid >> 4;

    // This block's 16 tokens are entirely in s1 or entirely in s2.
    const int* sp = (j0 < L) ? (s1 + b * L + j0) : (s2 + b * L + (j0 - L));

    int toks[TOKS_PER_BLOCK];
    #pragma unroll
    for (int k = 0; k < TOKS_PER_BLOCK; k++)
        toks[k] = __ldg(&sp[k]);

    const float sw0 = __ldg(&sos[wg]);
    const float sw1 = __ldg(&sos[wg + 16]);
    const float sw2 = __ldg(&sos[wg + 32]);
    const float sw3 = __ldg(&sos[wg + 48]);

    float4 acc = make_float4(0.f, 0.f, 0.f, 0.f);

    #pragma unroll 8
    for (int k = 0; k < TOKS_PER_BLOCK; k++) {
        const float4* M = embed + (size_t)toks[k] * (H * H / 4);

        float4 m0 = __ldg(&M[(wg      ) * 16 + h4]);
        float4 m1 = __ldg(&M[(wg + 16) * 16 + h4]);
        float4 m2 = __ldg(&M[(wg + 32) * 16 + h4]);
        float4 m3 = __ldg(&M[(wg + 48) * 16 + h4]);

        acc.x = fmaf(sw0, m0.x, acc.x); acc.y = fmaf(sw0, m0.y, acc.y);
        acc.z = fmaf(sw0, m0.z, acc.z); acc.w = fmaf(sw0, m0.w, acc.w);
        acc.x = fmaf(sw1, m1.x, acc.x); acc.y = fmaf(sw1, m1.y, acc.y);
        acc.z = fmaf(sw1, m1.z, acc.z); acc.w = fmaf(sw1, m1.w, acc.w);
        acc.x = fmaf(sw2, m2.x, acc.x); acc.y = fmaf(sw2, m2.y, acc.y);
        acc.z = fmaf(sw2, m2.z, acc.z); acc.w = fmaf(sw2, m2.w, acc.w);
        acc.x = fmaf(sw3, m3.x, acc.x); acc.y = fmaf(sw3, m3.y, acc.y);
        acc.z = fmaf(sw3, m3.z, acc.z); acc.w = fmaf(sw3, m3.w, acc.w);
    }

    // Warp reduce: lane l and l+16 hold the same columns for adjacent wg rows.
    acc.x += __shfl_down_sync(0xffffffffu, acc.x, 16);
    acc.y += __shfl_down_sync(0xffffffffu, acc.y, 16);
    acc.z += __shfl_down_sync(0xffffffffu, acc.z, 16);
    acc.w += __shfl_down_sync(0xffffffffu, acc.w, 16);

    __shared__ float sh[8][H];
    __shared__ float sv[H];            // block-partial h
    __shared__ float part[4][H];       // first-layer partial products
    const int warp = tid >> 5;
    const int lane = tid & 31;
    if (lane < 16) {
        sh[warp][lane * 4 + 0] = acc.x;
        sh[warp][lane * 4 + 1] = acc.y;
        sh[warp][lane * 4 + 2] = acc.z;
        sh[warp][lane * 4 + 3] = acc.w;
    }
    __syncthreads();
    if (tid < H) {
        float s = 0.f;
        #pragma unroll
        for (int w = 0; w < 8; w++) s += sh[w][tid];
        sv[tid] = s;
    }
    __syncthreads();

    // First layer partial: thread (q = tid>>6, j = tid&63) does the q-th
    // 16-k slice of y[j] = sum_k sv[k]*w1[j*H+k]. w1 is hot in L1 after the
    // first block on each SM.
    {
        const int q = tid >> 6;
        const int j = tid & 63;
        float p = 0.f;
        #pragma unroll
        for (int k = q * 16; k < q * 16 + 16; k++)
            p = fmaf(sv[k], __ldg(&w1[j * H + k]), p);
        part[q][j] = p;
    }
    __syncthreads();
    if (tid < H) {
        const float yj = part[0][tid] + part[1][tid]
                       + part[2][tid] + part[3][tid];
        atomicAdd(&g_y[b * H + tid], yj);
    }
}

// ---------------------------------------------------------------------------
// Kernel 2: tiny epilogue — relu(y + b1) @ w2^T + b2. One block, 128 threads.
// Stages y coalesced into smem, resets g_y for the next replay, then 32
// threads compute the 32 outputs.
// ---------------------------------------------------------------------------
__global__ __launch_bounds__(128, 1)
void epilogue_kernel(const float* __restrict__ b1,
                     const float* __restrict__ w2,
                     const float* __restrict__ b2,
                     float* __restrict__ out)
{
    __shared__ float x[B * H];
    const int tid = threadIdx.x;       // 0..127

    #pragma unroll
    for (int i = tid; i < B * H; i += 128) {
        const float v = g_y[i] + __ldg(&b1[i & 63]);
        x[i] = fmaxf(v, 0.f);
        g_y[i] = 0.0f;                 // reset for next graph replay
    }
    __syncthreads();

    if (tid < B * OUT) {
        const int b = tid >> 1;
        const int o = tid & 1;
        float a = __ldg(&b2[o]);
        #pragma unroll
        for (int k = 0; k < H; k++)
            a = fmaf(x[b * H + k], __ldg(&w2[o * H + k]), a);
        out[b * OUT + o] = a;
    }
}

// ---------------------------------------------------------------------------
// Launch
// Inputs (metadata order): s1, s2, embed, sos, w1, b1, w2, b2
// ---------------------------------------------------------------------------
extern "C" void kernel_launch(void* const* d_in, const int* in_sizes, int n_in,
                              void* d_out, int out_size)
{
    const int*    s1    = (const int*)   d_in[0];
    const int*    s2    = (const int*)   d_in[1];
    const float4* embed = (const float4*)d_in[2];
    const float*  sos   = (const float*) d_in[3];
    const float*  w1    = (const float*) d_in[4];
    const float*  b1    = (const float*) d_in[5];
    const float*  w2    = (const float*) d_in[6];
    const float*  b2    = (const float*) d_in[7];
    float* out = (float*)d_out;

    gather_contract_kernel<<<GRID1, 256>>>(s1, s2, embed, sos, w1);
    epilogue_kernel<<<1, 128>>>(b1, w2, b2, out);
}

// round 13
// speedup vs baseline: 1.2749x; 1.2749x over previous
#include <cuda_runtime.h>
#include <cuda_bf16.h>
#include <cstdint>

// Problem constants
#define H 64
#define B 16
#define L 512
#define OUT 2
#define TOKS_PER_BLOCK 16
#define BLOCKS_PER_BATCH (2 * L / TOKS_PER_BLOCK)    // 64
#define GRID1 (B * BLOCKS_PER_BATCH)                 // 1024

// Accumulator + completion counter. Zero at module load; the finishing block
// resets both after use, so every graph replay sees them zeroed.
__device__ float g_h[B * H];
__device__ unsigned int g_count;

// ---------------------------------------------------------------------------
// Fused kernel: R9's proven gather (64-reg budget) + last-block MLP epilogue.
// (R12 = R11 resubmitted unchanged after a GB300 container infra failure.)
// R4/R5's fused regression is attributed to the 32-reg cap (spills in the
// main loop), not the fence: this version keeps __launch_bounds__(256,4).
// ---------------------------------------------------------------------------
__global__ __launch_bounds__(256, 4)
void fused_kernel(const int* __restrict__ s1,
                  const int* __restrict__ s2,
                  const float4* __restrict__ embed,
                  const float* __restrict__ sos,
                  const float* __restrict__ w1,
                  const float* __restrict__ b1,
                  const float* __restrict__ w2,
                  const float* __restrict__ b2,
                  float* __restrict__ out)
{
    __shared__ union {
        float sh[8][H];                    // gather cross-warp reduce (2KB)
        struct {                           // epilogue (~24.6KB)
            float w1s[H][H + 1];
            float hs[B * H];
            float x[B][H];
        } epi;
    } u;
    __shared__ unsigned int is_last;

    const int bl  = blockIdx.x;
    const int b   = bl / BLOCKS_PER_BATCH;
    const int j0  = (bl % BLOCKS_PER_BATCH) * TOKS_PER_BLOCK;  // within [0, 1024)
    const int tid = threadIdx.x;
    const int h4  = tid & 15;
    const int wg  = tid >> 4;

    // This block's 16 tokens are entirely in s1 or entirely in s2.
    const int* sp = (j0 < L) ? (s1 + b * L + j0) : (s2 + b * L + (j0 - L));

    int toks[TOKS_PER_BLOCK];
    #pragma unroll
    for (int k = 0; k < TOKS_PER_BLOCK; k++)
        toks[k] = __ldg(&sp[k]);

    const float sw0 = __ldg(&sos[wg]);
    const float sw1 = __ldg(&sos[wg + 16]);
    const float sw2 = __ldg(&sos[wg + 32]);
    const float sw3 = __ldg(&sos[wg + 48]);

    float4 acc = make_float4(0.f, 0.f, 0.f, 0.f);

    #pragma unroll 8
    for (int k = 0; k < TOKS_PER_BLOCK; k++) {
        const float4* M = embed + (size_t)toks[k] * (H * H / 4);

        float4 m0 = __ldg(&M[(wg      ) * 16 + h4]);
        float4 m1 = __ldg(&M[(wg + 16) * 16 + h4]);
        float4 m2 = __ldg(&M[(wg + 32) * 16 + h4]);
        float4 m3 = __ldg(&M[(wg + 48) * 16 + h4]);

        acc.x = fmaf(sw0, m0.x, acc.x); acc.y = fmaf(sw0, m0.y, acc.y);
        acc.z = fmaf(sw0, m0.z, acc.z); acc.w = fmaf(sw0, m0.w, acc.w);
        acc.x = fmaf(sw1, m1.x, acc.x); acc.y = fmaf(sw1, m1.y, acc.y);
        acc.z = fmaf(sw1, m1.z, acc.z); acc.w = fmaf(sw1, m1.w, acc.w);
        acc.x = fmaf(sw2, m2.x, acc.x); acc.y = fmaf(sw2, m2.y, acc.y);
        acc.z = fmaf(sw2, m2.z, acc.z); acc.w = fmaf(sw2, m2.w, acc.w);
        acc.x = fmaf(sw3, m3.x, acc.x); acc.y = fmaf(sw3, m3.y, acc.y);
        acc.z = fmaf(sw3, m3.z, acc.z); acc.w = fmaf(sw3, m3.w, acc.w);
    }

    // Warp reduce: lane l and l+16 hold the same columns for adjacent wg rows.
    acc.x += __shfl_down_sync(0xffffffffu, acc.x, 16);
    acc.y += __shfl_down_sync(0xffffffffu, acc.y, 16);
    acc.z += __shfl_down_sync(0xffffffffu, acc.z, 16);
    acc.w += __shfl_down_sync(0xffffffffu, acc.w, 16);

    const int warp = tid >> 5;
    const int lane = tid & 31;
    if (lane < 16) {
        u.sh[warp][lane * 4 + 0] = acc.x;
        u.sh[warp][lane * 4 + 1] = acc.y;
        u.sh[warp][lane * 4 + 2] = acc.z;
        u.sh[warp][lane * 4 + 3] = acc.w;
    }
    __syncthreads();
    if (tid < H) {
        float s = 0.f;
        #pragma unroll
        for (int w = 0; w < 8; w++) s += u.sh[w][tid];
        atomicAdd(&g_h[b * H + tid], s);
    }

    // ---- completion detection -------------------------------------------
    __threadfence();                     // order g_h atomics before counter
    __syncthreads();                     // all reads of u.sh done
    if (tid == 0)
        is_last = (atomicAdd(&g_count, 1u) == GRID1 - 1u) ? 1u : 0u;
    __syncthreads();
    if (!is_last) return;
    __threadfence();                     // acquire: see all g_h updates

    // ---- MLP epilogue (last block only, 256 threads) --------------------
    // out = relu(h @ w1^T + b1) @ w2^T + b2
    #pragma unroll
    for (int idx = tid; idx < H * H; idx += 256)
        u.epi.w1s[idx >> 6][idx & 63] = __ldg(&w1[idx]);
    #pragma unroll
    for (int idx = tid; idx < B * H; idx += 256) {
        u.epi.hs[idx] = __ldcg(&g_h[idx]);   // L2 read (producers used L2 atomics)
        g_h[idx] = 0.0f;                     // reset for next graph replay
    }
    __syncthreads();

    // First layer: thread (q = tid>>6 -> batches q,q+4,q+8,q+12; j = tid&63).
    {
        const int j  = tid & 63;
        const int q  = tid >> 6;
        const float bj = __ldg(&b1[j]);
        #pragma unroll
        for (int r = 0; r < 4; r++) {
            const int bb = q + r * 4;
            float a = bj;
            #pragma unroll
            for (int k = 0; k < H; k++)
                a = fmaf(u.epi.hs[bb * H + k], u.epi.w1s[j][k], a);
            u.epi.x[bb][j] = fmaxf(a, 0.f);
        }
    }
    __syncthreads();

    // Second layer: 32 outputs.
    if (tid < B * OUT) {
        const int bb = tid >> 1;
        const int o  = tid & 1;
        float a = __ldg(&b2[o]);
        #pragma unroll
        for (int k = 0; k < H; k++)
            a = fmaf(u.epi.x[bb][k], __ldg(&w2[o * H + k]), a);
        out[bb * OUT + o] = a;
    }

    if (tid == 0) g_count = 0u;              // reset counter for next replay
}

// ---------------------------------------------------------------------------
// Launch
// Inputs (metadata order): s1, s2, embed, sos, w1, b1, w2, b2
// ---------------------------------------------------------------------------
extern "C" void kernel_launch(void* const* d_in, const int* in_sizes, int n_in,
                              void* d_out, int out_size)
{
    const int*    s1    = (const int*)   d_in[0];
    const int*    s2    = (const int*)   d_in[1];
    const float4* embed = (const float4*)d_in[2];
    const float*  sos   = (const float*) d_in[3];
    const float*  w1    = (const float*) d_in[4];
    const float*  b1    = (const float*) d_in[5];
    const float*  w2    = (const float*) d_in[6];
    const float*  b2    = (const float*) d_in[7];
    float* out = (float*)d_out;

    fused_kernel<<<GRID1, 256>>>(s1, s2, embed, sos, w1, b1, w2, b2, out);
}

// round 15
// speedup vs baseline: 1.2986x; 1.0186x over previous
#include <cuda_runtime.h>
#include <cuda_bf16.h>
#include <cstdint>

// Problem constants
#define H 64
#define B 16
#define L 512
#define OUT 2
#define TOKS_PER_BLOCK 16
#define BLOCKS_PER_BATCH (2 * L / TOKS_PER_BLOCK)    // 64
#define GRID1 (B * BLOCKS_PER_BATCH)                 // 1024

// Accumulator + completion counter. Zero at module load; the finishing block
// resets both after use, so every graph replay sees them zeroed.
__device__ float g_h[B * H];
__device__ unsigned int g_count;

// ---------------------------------------------------------------------------
// Fused kernel, R15 = R14 resubmitted unchanged (GB300 infra failure).
// FENCE-FREE completion protocol: all cross-block traffic is L2-native
// (ATOMG g_h adds, ATOMG counter, LDG.cg reads), so no __threadfence
// (= MEMBAR.GL + CCTL.IVALL L1-flush per block, the R13 suspect) is needed.
// Completion-at-L2 of each block's adds is enforced by CONSUMING the
// atomicAdd return values before the barrier that precedes the counter bump.
// ---------------------------------------------------------------------------
__global__ __launch_bounds__(256, 4)
void fused_kernel(const int* __restrict__ s1,
                  const int* __restrict__ s2,
                  const float4* __restrict__ embed,
                  const float* __restrict__ sos,
                  const float* __restrict__ w1,
                  const float* __restrict__ b1,
                  const float* __restrict__ w2,
                  const float* __restrict__ b2,
                  float* __restrict__ out)
{
    __shared__ union {
        float sh[8][H];                    // gather cross-warp reduce (2KB)
        struct {                           // epilogue (~24.6KB)
            float w1s[H][H + 1];
            float hs[B * H];
            float x[B][H];
        } epi;
    } u;
    __shared__ unsigned int is_last;

    const int bl  = blockIdx.x;
    const int b   = bl / BLOCKS_PER_BATCH;
    const int j0  = (bl % BLOCKS_PER_BATCH) * TOKS_PER_BLOCK;  // within [0, 1024)
    const int tid = threadIdx.x;
    const int h4  = tid & 15;
    const int wg  = tid >> 4;

    // This block's 16 tokens are entirely in s1 or entirely in s2.
    const int* sp = (j0 < L) ? (s1 + b * L + j0) : (s2 + b * L + (j0 - L));

    int toks[TOKS_PER_BLOCK];
    #pragma unroll
    for (int k = 0; k < TOKS_PER_BLOCK; k++)
        toks[k] = __ldg(&sp[k]);

    const float sw0 = __ldg(&sos[wg]);
    const float sw1 = __ldg(&sos[wg + 16]);
    const float sw2 = __ldg(&sos[wg + 32]);
    const float sw3 = __ldg(&sos[wg + 48]);

    float4 acc = make_float4(0.f, 0.f, 0.f, 0.f);

    #pragma unroll 8
    for (int k = 0; k < TOKS_PER_BLOCK; k++) {
        const float4* M = embed + (size_t)toks[k] * (H * H / 4);

        float4 m0 = __ldg(&M[(wg      ) * 16 + h4]);
        float4 m1 = __ldg(&M[(wg + 16) * 16 + h4]);
        float4 m2 = __ldg(&M[(wg + 32) * 16 + h4]);
        float4 m3 = __ldg(&M[(wg + 48) * 16 + h4]);

        acc.x = fmaf(sw0, m0.x, acc.x); acc.y = fmaf(sw0, m0.y, acc.y);
        acc.z = fmaf(sw0, m0.z, acc.z); acc.w = fmaf(sw0, m0.w, acc.w);
        acc.x = fmaf(sw1, m1.x, acc.x); acc.y = fmaf(sw1, m1.y, acc.y);
        acc.z = fmaf(sw1, m1.z, acc.z); acc.w = fmaf(sw1, m1.w, acc.w);
        acc.x = fmaf(sw2, m2.x, acc.x); acc.y = fmaf(sw2, m2.y, acc.y);
        acc.z = fmaf(sw2, m2.z, acc.z); acc.w = fmaf(sw2, m2.w, acc.w);
        acc.x = fmaf(sw3, m3.x, acc.x); acc.y = fmaf(sw3, m3.y, acc.y);
        acc.z = fmaf(sw3, m3.z, acc.z); acc.w = fmaf(sw3, m3.w, acc.w);
    }

    // Warp reduce: lane l and l+16 hold the same columns for adjacent wg rows.
    acc.x += __shfl_down_sync(0xffffffffu, acc.x, 16);
    acc.y += __shfl_down_sync(0xffffffffu, acc.y, 16);
    acc.z += __shfl_down_sync(0xffffffffu, acc.z, 16);
    acc.w += __shfl_down_sync(0xffffffffu, acc.w, 16);

    const int warp = tid >> 5;
    const int lane = tid & 31;
    if (lane < 16) {
        u.sh[warp][lane * 4 + 0] = acc.x;
        u.sh[warp][lane * 4 + 1] = acc.y;
        u.sh[warp][lane * 4 + 2] = acc.z;
        u.sh[warp][lane * 4 + 3] = acc.w;
    }
    __syncthreads();
    if (tid < H) {
        float s = 0.f;
        #pragma unroll
        for (int w = 0; w < 8; w++) s += u.sh[w][tid];
        // L2 atomic; CONSUME the return value so the SB-wait forces the add
        // to be complete (globally visible at L2) before we pass the barrier.
        const float old = atomicAdd(&g_h[b * H + tid], s);
        // Impossible condition (NaN payload compare) the compiler cannot fold:
        if (__float_as_uint(old) == 0x7f800001u) out[0] = s;
    }

    // ---- completion detection (no fences) -------------------------------
    __syncthreads();                     // all 64 adds of this block completed
    if (tid == 0)
        is_last = (atomicAdd(&g_count, 1u) == GRID1 - 1u) ? 1u : 0u;
    __syncthreads();
    if (!is_last) return;

    // ---- MLP epilogue (last block only, 256 threads) --------------------
    // out = relu(h @ w1^T + b1) @ w2^T + b2
    #pragma unroll
    for (int idx = tid; idx < H * H; idx += 256)
        u.epi.w1s[idx >> 6][idx & 63] = __ldg(&w1[idx]);
    #pragma unroll
    for (int idx = tid; idx < B * H; idx += 256) {
        u.epi.hs[idx] = __ldcg(&g_h[idx]);   // direct L2 read
        g_h[idx] = 0.0f;                     // reset for next graph replay
    }
    __syncthreads();

    // First layer: thread (q = tid>>6 -> batches q,q+4,q+8,q+12; j = tid&63).
    {
        const int j  = tid & 63;
        const int q  = tid >> 6;
        const float bj = __ldg(&b1[j]);
        #pragma unroll
        for (int r = 0; r < 4; r++) {
            const int bb = q + r * 4;
            float a = bj;
            #pragma unroll
            for (int k = 0; k < H; k++)
                a = fmaf(u.epi.hs[bb * H + k], u.epi.w1s[j][k], a);
            u.epi.x[bb][j] = fmaxf(a, 0.f);
        }
    }
    __syncthreads();

    // Second layer: 32 outputs.
    if (tid < B * OUT) {
        const int bb = tid >> 1;
        const int o  = tid & 1;
        float a = __ldg(&b2[o]);
        #pragma unroll
        for (int k = 0; k < H; k++)
            a = fmaf(u.epi.x[bb][k], __ldg(&w2[o * H + k]), a);
        out[bb * OUT + o] = a;
    }

    if (tid == 0) g_count = 0u;              // reset counter for next replay
}

// ---------------------------------------------------------------------------
// Launch
// Inputs (metadata order): s1, s2, embed, sos, w1, b1, w2, b2
// ---------------------------------------------------------------------------
extern "C" void kernel_launch(void* const* d_in, const int* in_sizes, int n_in,
                              void* d_out, int out_size)
{
    const int*    s1    = (const int*)   d_in[0];
    const int*    s2    = (const int*)   d_in[1];
    const float4* embed = (const float4*)d_in[2];
    const float*  sos   = (const float*) d_in[3];
    const float*  w1    = (const float*) d_in[4];
    const float*  b1    = (const float*) d_in[5];
    const float*  w2    = (const float*) d_in[6];
    const float*  b2    = (const float*) d_in[7];
    float* out = (float*)d_out;

    fused_kernel<<<GRID1, 256>>>(s1, s2, embed, sos, w1, b1, w2, b2, out);
}

// round 16
// speedup vs baseline: 1.3374x; 1.0299x over previous
#include <cuda_runtime.h>
#include <cuda_bf16.h>
#include <cstdint>

// Problem constants
#define H 64
#define B 16
#define L 512
#define OUT 2
#define TOKS_PER_BLOCK 16
#define BLOCKS_PER_BATCH (2 * L / TOKS_PER_BLOCK)    // 64
#define GRID1 (B * BLOCKS_PER_BATCH)                 // 1024

// Per-batch accumulators + per-batch completion counters. Zero at module
// load; each batch's finishing block resets its slice, so graph replays are
// deterministic.
__device__ float        g_h[B * H];
__device__ unsigned int g_bcount[B];
__device__ float        g_dummy;

// ---------------------------------------------------------------------------
// Fused kernel, R16: PER-BATCH completion. The last block of each batch (64
// blocks/batch) runs a tiny warp-cooperative epilogue for just that batch's
// 2 outputs. Smem stays 2KB (no fat union -> full L1D carveout), no fences
// (L2-native protocol: atomicAdd returns consumed before the counter bump),
// and the 16 mini-epilogues overlap with still-running gather blocks.
// ---------------------------------------------------------------------------
__global__ __launch_bounds__(256, 4)
void fused_kernel(const int* __restrict__ s1,
                  const int* __restrict__ s2,
                  const float4* __restrict__ embed,
                  const float* __restrict__ sos,
                  const float* __restrict__ w1,
                  const float* __restrict__ b1,
                  const float* __restrict__ w2,
                  const float* __restrict__ b2,
                  float* __restrict__ out)
{
    __shared__ float sh[8][H];             // gather reduce; reused by epilogue
    __shared__ unsigned int is_last;

    const int bl  = blockIdx.x;
    const int b   = bl / BLOCKS_PER_BATCH;
    const int j0  = (bl % BLOCKS_PER_BATCH) * TOKS_PER_BLOCK;  // within [0, 1024)
    const int tid = threadIdx.x;
    const int h4  = tid & 15;
    const int wg  = tid >> 4;

    // This block's 16 tokens are entirely in s1 or entirely in s2.
    const int* sp = (j0 < L) ? (s1 + b * L + j0) : (s2 + b * L + (j0 - L));

    int toks[TOKS_PER_BLOCK];
    #pragma unroll
    for (int k = 0; k < TOKS_PER_BLOCK; k++)
        toks[k] = __ldg(&sp[k]);

    const float sw0 = __ldg(&sos[wg]);
    const float sw1 = __ldg(&sos[wg + 16]);
    const float sw2 = __ldg(&sos[wg + 32]);
    const float sw3 = __ldg(&sos[wg + 48]);

    float4 acc = make_float4(0.f, 0.f, 0.f, 0.f);

    #pragma unroll 8
    for (int k = 0; k < TOKS_PER_BLOCK; k++) {
        const float4* M = embed + (size_t)toks[k] * (H * H / 4);

        float4 m0 = __ldg(&M[(wg      ) * 16 + h4]);
        float4 m1 = __ldg(&M[(wg + 16) * 16 + h4]);
        float4 m2 = __ldg(&M[(wg + 32) * 16 + h4]);
        float4 m3 = __ldg(&M[(wg + 48) * 16 + h4]);

        acc.x = fmaf(sw0, m0.x, acc.x); acc.y = fmaf(sw0, m0.y, acc.y);
        acc.z = fmaf(sw0, m0.z, acc.z); acc.w = fmaf(sw0, m0.w, acc.w);
        acc.x = fmaf(sw1, m1.x, acc.x); acc.y = fmaf(sw1, m1.y, acc.y);
        acc.z = fmaf(sw1, m1.z, acc.z); acc.w = fmaf(sw1, m1.w, acc.w);
        acc.x = fmaf(sw2, m2.x, acc.x); acc.y = fmaf(sw2, m2.y, acc.y);
        acc.z = fmaf(sw2, m2.z, acc.z); acc.w = fmaf(sw2, m2.w, acc.w);
        acc.x = fmaf(sw3, m3.x, acc.x); acc.y = fmaf(sw3, m3.y, acc.y);
        acc.z = fmaf(sw3, m3.z, acc.z); acc.w = fmaf(sw3, m3.w, acc.w);
    }

    // Warp reduce: lane l and l+16 hold the same columns for adjacent wg rows.
    acc.x += __shfl_down_sync(0xffffffffu, acc.x, 16);
    acc.y += __shfl_down_sync(0xffffffffu, acc.y, 16);
    acc.z += __shfl_down_sync(0xffffffffu, acc.z, 16);
    acc.w += __shfl_down_sync(0xffffffffu, acc.w, 16);

    const int warp = tid >> 5;
    const int lane = tid & 31;
    if (lane < 16) {
        sh[warp][lane * 4 + 0] = acc.x;
        sh[warp][lane * 4 + 1] = acc.y;
        sh[warp][lane * 4 + 2] = acc.z;
        sh[warp][lane * 4 + 3] = acc.w;
    }
    __syncthreads();
    if (tid < H) {
        float s = 0.f;
        #pragma unroll
        for (int w = 0; w < 8; w++) s += sh[w][tid];
        // L2 atomic; CONSUME the return value: the SB-wait guarantees the
        // add completed (visible at L2) before this thread passes the barrier.
        const float old = atomicAdd(&g_h[b * H + tid], s);
        if (__float_as_uint(old) == 0x7f800001u) g_dummy = s;  // never true
    }

    // ---- per-batch completion (no fences) -------------------------------
    __syncthreads();                     // all 64 adds of this block complete
    if (tid == 0)
        is_last = (atomicAdd(&g_bcount[b], 1u) == BLOCKS_PER_BATCH - 1u) ? 1u : 0u;
    __syncthreads();
    if (!is_last) return;

    // ---- epilogue for THIS batch only (256 threads, 8 warps) ------------
    // out[b] = relu(h[b] @ w1^T + b1) @ w2^T + b2
    float* xh = &sh[0][0];               // h row     (64 floats)
    float* sy = &sh[1][0];               // relu(y)   (64 floats)

    if (tid < H) {
        xh[tid] = __ldcg(&g_h[b * H + tid]);  // direct L2 read
        g_h[b * H + tid] = 0.0f;              // reset for next replay
    }
    __syncthreads();

    // Warp w -> hidden rows j = w*8 .. w*8+7. Coalesced w1 row loads,
    // shuffle reduction (this scheme was clean in R5; only 16 blocks chip-
    // wide run it here, staggered in time).
    #pragma unroll
    for (int r = 0; r < 8; r++) {
        const int j = warp * 8 + r;
        const float wa = __ldg(&w1[j * H + lane]);
        const float wb = __ldg(&w1[j * H + 32 + lane]);
        float p = xh[lane] * wa + xh[32 + lane] * wb;
        p += __shfl_down_sync(0xffffffffu, p, 16);
        p += __shfl_down_sync(0xffffffffu, p, 8);
        p += __shfl_down_sync(0xffffffffu, p, 4);
        p += __shfl_down_sync(0xffffffffu, p, 2);
        p += __shfl_down_sync(0xffffffffu, p, 1);
        if (lane == 0) sy[j] = fmaxf(p + __ldg(&b1[j]), 0.f);
    }
    __syncthreads();

    // Second layer: 2 outputs for this batch (warp-cooperative, warp 0).
    if (warp == 0) {
        #pragma unroll
        for (int o = 0; o < OUT; o++) {
            float p = sy[lane] * __ldg(&w2[o * H + lane])
                    + sy[32 + lane] * __ldg(&w2[o * H + 32 + lane]);
            p += __shfl_down_sync(0xffffffffu, p, 16);
            p += __shfl_down_sync(0xffffffffu, p, 8);
            p += __shfl_down_sync(0xffffffffu, p, 4);
            p += __shfl_down_sync(0xffffffffu, p, 2);
            p += __shfl_down_sync(0xffffffffu, p, 1);
            if (lane == 0) out[b * OUT + o] = p + __ldg(&b2[o]);
        }
        if (lane == 0) g_bcount[b] = 0u;     // reset for next replay
    }
}

// ---------------------------------------------------------------------------
// Launch
// Inputs (metadata order): s1, s2, embed, sos, w1, b1, w2, b2
// ---------------------------------------------------------------------------
extern "C" void kernel_launch(void* const* d_in, const int* in_sizes, int n_in,
                              void* d_out, int out_size)
{
    const int*    s1    = (const int*)   d_in[0];
    const int*    s2    = (const int*)   d_in[1];
    const float4* embed = (const float4*)d_in[2];
    const float*  sos   = (const float*) d_in[3];
    const float*  w1    = (const float*) d_in[4];
    const float*  b1    = (const float*) d_in[5];
    const float*  w2    = (const float*) d_in[6];
    const float*  b2    = (const float*) d_in[7];
    float* out = (float*)d_out;

    fused_kernel<<<GRID1, 256>>>(s1, s2, embed, sos, w1, b1, w2, b2, out);
}